// round 7
// baseline (speedup 1.0000x reference)
#include <cuda_runtime.h>
#include <math.h>
#include <cstdint>

// Problem constants
#define NN 512
#define CC 128
#define MM (NN*NN)          // 262144 rows

// ---------------- scratch (device globals: allocation-free) ----------------
__device__ float g_AT[(size_t)CC * MM];
__device__ float g_BT[(size_t)CC * MM];
__device__ float g_GL[(size_t)CC * MM];
__device__ float g_TRIT[(size_t)CC * MM];
__device__ float g_TRI [(size_t)CC * MM];
__device__ float g_mu1[MM];
__device__ float g_rs1[MM];

__device__ __forceinline__ float sigmoidf_(float x) {
    return 1.0f / (1.0f + expf(-x));
}

__device__ __forceinline__ float to_tf32(float x) {
    uint32_t u;
    asm("cvt.rna.tf32.f32 %0, %1;" : "=r"(u) : "f"(x));
    return __uint_as_float(u);
}

__device__ __forceinline__ void mma_tf32(float d[4], const uint32_t a[4], const uint32_t b[2]) {
    asm volatile(
        "mma.sync.aligned.m16n8k8.row.col.f32.tf32.tf32.f32 "
        "{%0,%1,%2,%3}, {%4,%5,%6,%7}, {%8,%9}, {%0,%1,%2,%3};"
        : "+f"(d[0]), "+f"(d[1]), "+f"(d[2]), "+f"(d[3])
        : "r"(a[0]), "r"(a[1]), "r"(a[2]), "r"(a[3]), "r"(b[0]), "r"(b[1]));
}

__device__ __forceinline__ uint32_t smem_u32(const void* p) {
    return (uint32_t)__cvta_generic_to_shared(p);
}
__device__ __forceinline__ void cp_async16(uint32_t sm, const void* gm) {
    asm volatile("cp.async.cg.shared.global [%0], [%1], 16;" :: "r"(sm), "l"(gm) : "memory");
}
__device__ __forceinline__ void cp_commit() {
    asm volatile("cp.async.commit_group;" ::: "memory");
}
template <int N>
__device__ __forceinline__ void cp_wait() {
    asm volatile("cp.async.wait_group %0;" :: "n"(N) : "memory");
}

// ---------------- LN1 row stats: one warp per 128-float row ----------------
__global__ __launch_bounds__(256) void k_stats(const float* __restrict__ src) {
    int row  = blockIdx.x * 8 + (threadIdx.x >> 5);
    int lane = threadIdx.x & 31;
    float4 v = reinterpret_cast<const float4*>(src + (size_t)row * CC)[lane];
    float sm = v.x + v.y + v.z + v.w;
    #pragma unroll
    for (int o = 16; o > 0; o >>= 1) sm += __shfl_xor_sync(0xffffffffu, sm, o);
    float m = sm * (1.0f / CC);
    float dx = v.x - m, dy = v.y - m, dz = v.z - m, dw = v.w - m;
    float q = dx*dx + dy*dy + dz*dz + dw*dw;
    #pragma unroll
    for (int o = 16; o > 0; o >>= 1) q += __shfl_xor_sync(0xffffffffu, q, o);
    if (lane == 0) {
        g_mu1[row] = m;
        g_rs1[row] = rsqrtf(q * (1.0f / CC) + 1e-5f);
    }
}

// ---------------- proj/gate (+gl) GEMM via mma.sync -------------------------
// Each CTA: 128 rows x 64 channels of (a or b). CTAs with off==0 additionally
// compute GL = sigmoid(x @ Wgl^T) for their 64 channels.
__global__ __launch_bounds__(256) void k_proj_mma(const float* __restrict__ pair,
                                                  const float* __restrict__ mask,
                                                  const float* __restrict__ w1,
                                                  const float* __restrict__ b1,
                                                  const float* __restrict__ Wp,
                                                  const float* __restrict__ Wg,
                                                  const float* __restrict__ Wgl) {
    __shared__ float As[128][36];
    __shared__ float Bs[192][36];   // 0..63 Wp, 64..127 Wg, 128..191 Wgl

    const int tid = threadIdx.x;
    const int wid = tid >> 5, lane = tid & 31;
    const int wm = wid >> 1, wn = wid & 1;
    const int grp = lane >> 2, qd = lane & 3;
    const int m0  = blockIdx.y * 128;
    const int c0  = (blockIdx.x & 1) * 64;
    const int off = blockIdx.x >> 1;
    const bool do_gl = (off == 0);

    float accP[2][4][4], accG[2][4][4], accL[2][4][4];
    #pragma unroll
    for (int mt = 0; mt < 2; mt++)
        #pragma unroll
        for (int nt = 0; nt < 4; nt++)
            #pragma unroll
            for (int r = 0; r < 4; r++) { accP[mt][nt][r] = 0.0f; accG[mt][nt][r] = 0.0f; accL[mt][nt][r] = 0.0f; }

    for (int kt = 0; kt < 4; kt++) {
        float4 va[4], vb[6];
        float lmu[4], lrs[4];
        #pragma unroll
        for (int r = 0; r < 4; r++) {
            int idx = tid + r * 256, row = idx >> 3, q = idx & 7;
            va[r] = *reinterpret_cast<const float4*>(pair + (size_t)(m0 + row) * CC + kt * 32 + q * 4);
            lmu[r] = g_mu1[m0 + row];
            lrs[r] = g_rs1[m0 + row];
        }
        #pragma unroll
        for (int r = 0; r < 6; r++) {
            int idx = tid + r * 256, row = idx >> 3, q = idx & 7;
            if (row < 64) {
                vb[r] = *reinterpret_cast<const float4*>(Wp + (size_t)(2 * (c0 + row) + off) * CC + kt * 32 + q * 4);
            } else if (row < 128) {
                vb[r] = *reinterpret_cast<const float4*>(Wg + (size_t)(2 * (c0 + row - 64) + off) * CC + kt * 32 + q * 4);
            } else if (do_gl) {
                vb[r] = *reinterpret_cast<const float4*>(Wgl + (size_t)(c0 + row - 128) * CC + kt * 32 + q * 4);
            } else {
                vb[r] = make_float4(0.f, 0.f, 0.f, 0.f);
            }
        }
        __syncthreads();
        #pragma unroll
        for (int r = 0; r < 4; r++) {
            int idx = tid + r * 256, row = idx >> 3, q = idx & 7;
            float4 wv = *reinterpret_cast<const float4*>(w1 + kt * 32 + q * 4);
            float4 bv = *reinterpret_cast<const float4*>(b1 + kt * 32 + q * 4);
            float4 ta = make_float4(
                to_tf32((va[r].x - lmu[r]) * lrs[r] * wv.x + bv.x),
                to_tf32((va[r].y - lmu[r]) * lrs[r] * wv.y + bv.y),
                to_tf32((va[r].z - lmu[r]) * lrs[r] * wv.z + bv.z),
                to_tf32((va[r].w - lmu[r]) * lrs[r] * wv.w + bv.w));
            *reinterpret_cast<float4*>(&As[row][q * 4]) = ta;
        }
        #pragma unroll
        for (int r = 0; r < 6; r++) {
            int idx = tid + r * 256, row = idx >> 3, q = idx & 7;
            float4 tb = make_float4(to_tf32(vb[r].x), to_tf32(vb[r].y),
                                    to_tf32(vb[r].z), to_tf32(vb[r].w));
            *reinterpret_cast<float4*>(&Bs[row][q * 4]) = tb;
        }
        __syncthreads();

        #pragma unroll
        for (int ks = 0; ks < 4; ks++) {
            const int kc = ks * 8 + qd;
            uint32_t af[2][4];
            #pragma unroll
            for (int mt = 0; mt < 2; mt++) {
                int rr = wm * 32 + mt * 16 + grp;
                af[mt][0] = __float_as_uint(As[rr    ][kc]);
                af[mt][1] = __float_as_uint(As[rr + 8][kc]);
                af[mt][2] = __float_as_uint(As[rr    ][kc + 4]);
                af[mt][3] = __float_as_uint(As[rr + 8][kc + 4]);
            }
            uint32_t bp[4][2], bg[4][2];
            #pragma unroll
            for (int nt = 0; nt < 4; nt++) {
                int nn = wn * 32 + nt * 8 + grp;
                bp[nt][0] = __float_as_uint(Bs[nn     ][kc]);
                bp[nt][1] = __float_as_uint(Bs[nn     ][kc + 4]);
                bg[nt][0] = __float_as_uint(Bs[64 + nn][kc]);
                bg[nt][1] = __float_as_uint(Bs[64 + nn][kc + 4]);
            }
            #pragma unroll
            for (int mt = 0; mt < 2; mt++)
                #pragma unroll
                for (int nt = 0; nt < 4; nt++) {
                    mma_tf32(accP[mt][nt], af[mt], bp[nt]);
                    mma_tf32(accG[mt][nt], af[mt], bg[nt]);
                }
            if (do_gl) {
                uint32_t bl[4][2];
                #pragma unroll
                for (int nt = 0; nt < 4; nt++) {
                    int nn = wn * 32 + nt * 8 + grp;
                    bl[nt][0] = __float_as_uint(Bs[128 + nn][kc]);
                    bl[nt][1] = __float_as_uint(Bs[128 + nn][kc + 4]);
                }
                #pragma unroll
                for (int mt = 0; mt < 2; mt++)
                    #pragma unroll
                    for (int nt = 0; nt < 4; nt++)
                        mma_tf32(accL[mt][nt], af[mt], bl[nt]);
            }
        }
    }

    float* __restrict__ dst = off ? g_BT : g_AT;
    #pragma unroll
    for (int mt = 0; mt < 2; mt++) {
        int ra = m0 + wm * 32 + mt * 16 + grp;
        int rb = ra + 8;
        float mka = mask[ra], mkb = mask[rb];
        #pragma unroll
        for (int nt = 0; nt < 4; nt++) {
            int ch = c0 + wn * 32 + nt * 8 + 2 * qd;
            dst[(size_t)ch * MM + ra]       = to_tf32(accP[mt][nt][0] * mka * sigmoidf_(accG[mt][nt][0]));
            dst[(size_t)(ch + 1) * MM + ra] = to_tf32(accP[mt][nt][1] * mka * sigmoidf_(accG[mt][nt][1]));
            dst[(size_t)ch * MM + rb]       = to_tf32(accP[mt][nt][2] * mkb * sigmoidf_(accG[mt][nt][2]));
            dst[(size_t)(ch + 1) * MM + rb] = to_tf32(accP[mt][nt][3] * mkb * sigmoidf_(accG[mt][nt][3]));
            if (do_gl) {
                *reinterpret_cast<float2*>(g_GL + (size_t)ra * CC + ch) =
                    make_float2(sigmoidf_(accL[mt][nt][0]), sigmoidf_(accL[mt][nt][1]));
                *reinterpret_cast<float2*>(g_GL + (size_t)rb * CC + ch) =
                    make_float2(sigmoidf_(accL[mt][nt][2]), sigmoidf_(accL[mt][nt][3]));
            }
        }
    }
}

// ---------------- triangle einsum: single-barrier cp.async pipeline ---------
__global__ __launch_bounds__(256, 2) void k_tri_mma() {
    __shared__ float As[2][128][20];
    __shared__ float Bs[2][128][20];

    const int tid  = threadIdx.x;
    const int wid  = tid >> 5;
    const int lane = tid & 31;
    const int wm   = wid >> 2;
    const int wn   = wid & 3;
    const int grp  = lane >> 2;
    const int qd   = lane & 3;

    const int c  = blockIdx.z;
    const int i0 = blockIdx.y * 128;
    const int j0 = blockIdx.x * 128;
    const float* __restrict__ A = g_AT + (size_t)c * MM + (size_t)i0 * NN;
    const float* __restrict__ B = g_BT + (size_t)c * MM + (size_t)j0 * NN;

    const int row0 = tid >> 2,         q0 = tid & 3;
    const int row1 = (tid + 256) >> 2, q1 = (tid + 256) & 3;

    float d[4][4][4];
    #pragma unroll
    for (int mt = 0; mt < 4; mt++)
        #pragma unroll
        for (int nt = 0; nt < 4; nt++)
            #pragma unroll
            for (int r = 0; r < 4; r++) d[mt][nt][r] = 0.0f;

    // prologue: stage kt=0 into buffer 0
    cp_async16(smem_u32(&As[0][row0][q0 * 4]), A + (size_t)row0 * NN + q0 * 4);
    cp_async16(smem_u32(&Bs[0][row0][q0 * 4]), B + (size_t)row0 * NN + q0 * 4);
    cp_async16(smem_u32(&As[0][row1][q1 * 4]), A + (size_t)row1 * NN + q1 * 4);
    cp_async16(smem_u32(&Bs[0][row1][q1 * 4]), B + (size_t)row1 * NN + q1 * 4);
    cp_commit();

    for (int kt = 0; kt < 32; kt++) {
        const int cur = kt & 1;
        cp_wait<0>();
        __syncthreads();                 // buf[cur] ready everywhere; kt-1 compute done everywhere
        if (kt < 31) {
            const int nxt = cur ^ 1;     // consumed at kt-1; safe to overwrite now
            const int ko = (kt + 1) * 16;
            cp_async16(smem_u32(&As[nxt][row0][q0 * 4]), A + (size_t)row0 * NN + ko + q0 * 4);
            cp_async16(smem_u32(&Bs[nxt][row0][q0 * 4]), B + (size_t)row0 * NN + ko + q0 * 4);
            cp_async16(smem_u32(&As[nxt][row1][q1 * 4]), A + (size_t)row1 * NN + ko + q1 * 4);
            cp_async16(smem_u32(&Bs[nxt][row1][q1 * 4]), B + (size_t)row1 * NN + ko + q1 * 4);
            cp_commit();
        }

        #pragma unroll
        for (int ks = 0; ks < 2; ks++) {
            const int kc = ks * 8 + qd;
            uint32_t af[4][4];
            #pragma unroll
            for (int mt = 0; mt < 4; mt++) {
                int rr = wm * 64 + mt * 16 + grp;
                af[mt][0] = __float_as_uint(As[cur][rr    ][kc]);
                af[mt][1] = __float_as_uint(As[cur][rr + 8][kc]);
                af[mt][2] = __float_as_uint(As[cur][rr    ][kc + 4]);
                af[mt][3] = __float_as_uint(As[cur][rr + 8][kc + 4]);
            }
            uint32_t bf[4][2];
            #pragma unroll
            for (int nt = 0; nt < 4; nt++) {
                int nn = wn * 32 + nt * 8 + grp;
                bf[nt][0] = __float_as_uint(Bs[cur][nn][kc]);
                bf[nt][1] = __float_as_uint(Bs[cur][nn][kc + 4]);
            }
            #pragma unroll
            for (int mt = 0; mt < 4; mt++)
                #pragma unroll
                for (int nt = 0; nt < 4; nt++)
                    mma_tf32(d[mt][nt], af[mt], bf[nt]);
        }
    }

    float* __restrict__ D = g_TRIT + (size_t)c * MM;
    #pragma unroll
    for (int mt = 0; mt < 4; mt++) {
        int r1 = i0 + wm * 64 + mt * 16 + grp;
        int r2 = r1 + 8;
        #pragma unroll
        for (int nt = 0; nt < 4; nt++) {
            int col = j0 + wn * 32 + nt * 8 + qd * 2;
            *reinterpret_cast<float2*>(D + (size_t)r1 * NN + col) = make_float2(d[mt][nt][0], d[mt][nt][1]);
            *reinterpret_cast<float2*>(D + (size_t)r2 * NN + col) = make_float2(d[mt][nt][2], d[mt][nt][3]);
        }
    }
}

// ---------------- transpose (C, M) -> (M, C): 64x64 float4 tiles ------------
__global__ __launch_bounds__(256) void k_transpose() {
    __shared__ float ts[64][65];
    const int m0 = blockIdx.x * 64;
    const int c0 = blockIdx.y * 64;
    const int t = threadIdx.x;
    #pragma unroll
    for (int r = 0; r < 4; r++) {
        int idx = t + r * 256;           // 0..1023
        int c = idx >> 4, f4 = idx & 15;
        float4 v = *reinterpret_cast<const float4*>(g_TRIT + (size_t)(c0 + c) * MM + m0 + f4 * 4);
        ts[c][f4 * 4 + 0] = v.x; ts[c][f4 * 4 + 1] = v.y;
        ts[c][f4 * 4 + 2] = v.z; ts[c][f4 * 4 + 3] = v.w;
    }
    __syncthreads();
    #pragma unroll
    for (int r = 0; r < 4; r++) {
        int idx = t + r * 256;
        int m = idx >> 4, fc = idx & 15;
        float4 v = make_float4(ts[fc * 4 + 0][m], ts[fc * 4 + 1][m],
                               ts[fc * 4 + 2][m], ts[fc * 4 + 3][m]);
        *reinterpret_cast<float4*>(g_TRI + (size_t)(m0 + m) * CC + c0 + fc * 4) = v;
    }
}

// ---------------- output: fused LN2 stats + GEMM + gate + residual ----------
__global__ __launch_bounds__(256) void k_out_mma(const float* __restrict__ pair,
                                                 const float* __restrict__ w2,
                                                 const float* __restrict__ b2,
                                                 const float* __restrict__ Wo,
                                                 float* __restrict__ out) {
    __shared__ float As[128][36];
    __shared__ float Bs[64][36];
    __shared__ float smu[128], srs[128];

    const int tid = threadIdx.x;
    const int wid = tid >> 5, lane = tid & 31;
    const int wm = wid >> 1, wn = wid & 1;
    const int grp = lane >> 2, qd = lane & 3;
    const int m0 = blockIdx.y * 128;
    const int c0 = blockIdx.x * 64;

    // Phase 1: LN2 stats for this CTA's 128 rows (16 rows per warp)
    for (int r = 0; r < 16; r++) {
        int row = wid * 16 + r;
        float4 v = reinterpret_cast<const float4*>(g_TRI + (size_t)(m0 + row) * CC)[lane];
        float sm = v.x + v.y + v.z + v.w;
        float sq = v.x*v.x + v.y*v.y + v.z*v.z + v.w*v.w;
        #pragma unroll
        for (int o = 16; o > 0; o >>= 1) {
            sm += __shfl_xor_sync(0xffffffffu, sm, o);
            sq += __shfl_xor_sync(0xffffffffu, sq, o);
        }
        if (lane == 0) {
            float m = sm * (1.0f / CC);
            float var = sq * (1.0f / CC) - m * m;
            smu[row] = m;
            srs[row] = rsqrtf(var + 1e-5f);
        }
    }
    __syncthreads();

    float acc[2][4][4];
    #pragma unroll
    for (int mt = 0; mt < 2; mt++)
        #pragma unroll
        for (int nt = 0; nt < 4; nt++)
            #pragma unroll
            for (int r = 0; r < 4; r++) acc[mt][nt][r] = 0.0f;

    for (int kt = 0; kt < 4; kt++) {
        float4 va[4], vb[2];
        float lmu[4], lrs[4];
        #pragma unroll
        for (int r = 0; r < 4; r++) {
            int idx = tid + r * 256, row = idx >> 3, q = idx & 7;
            va[r] = *reinterpret_cast<const float4*>(g_TRI + (size_t)(m0 + row) * CC + kt * 32 + q * 4);
            lmu[r] = smu[row];
            lrs[r] = srs[row];
        }
        #pragma unroll
        for (int r = 0; r < 2; r++) {
            int idx = tid + r * 256;
            int row = idx >> 3, q = idx & 7;
            vb[r] = *reinterpret_cast<const float4*>(Wo + (size_t)(c0 + row) * CC + kt * 32 + q * 4);
        }
        __syncthreads();
        #pragma unroll
        for (int r = 0; r < 4; r++) {
            int idx = tid + r * 256, row = idx >> 3, q = idx & 7;
            float4 wv = *reinterpret_cast<const float4*>(w2 + kt * 32 + q * 4);
            float4 bv = *reinterpret_cast<const float4*>(b2 + kt * 32 + q * 4);
            float4 ta = make_float4(
                to_tf32((va[r].x - lmu[r]) * lrs[r] * wv.x + bv.x),
                to_tf32((va[r].y - lmu[r]) * lrs[r] * wv.y + bv.y),
                to_tf32((va[r].z - lmu[r]) * lrs[r] * wv.z + bv.z),
                to_tf32((va[r].w - lmu[r]) * lrs[r] * wv.w + bv.w));
            *reinterpret_cast<float4*>(&As[row][q * 4]) = ta;
        }
        #pragma unroll
        for (int r = 0; r < 2; r++) {
            int idx = tid + r * 256, row = idx >> 3, q = idx & 7;
            float4 tb = make_float4(to_tf32(vb[r].x), to_tf32(vb[r].y),
                                    to_tf32(vb[r].z), to_tf32(vb[r].w));
            *reinterpret_cast<float4*>(&Bs[row][q * 4]) = tb;
        }
        __syncthreads();

        #pragma unroll
        for (int ks = 0; ks < 4; ks++) {
            const int kc = ks * 8 + qd;
            uint32_t af[2][4];
            #pragma unroll
            for (int mt = 0; mt < 2; mt++) {
                int rr = wm * 32 + mt * 16 + grp;
                af[mt][0] = __float_as_uint(As[rr    ][kc]);
                af[mt][1] = __float_as_uint(As[rr + 8][kc]);
                af[mt][2] = __float_as_uint(As[rr    ][kc + 4]);
                af[mt][3] = __float_as_uint(As[rr + 8][kc + 4]);
            }
            uint32_t bf[4][2];
            #pragma unroll
            for (int nt = 0; nt < 4; nt++) {
                int nn = wn * 32 + nt * 8 + grp;
                bf[nt][0] = __float_as_uint(Bs[nn][kc]);
                bf[nt][1] = __float_as_uint(Bs[nn][kc + 4]);
            }
            #pragma unroll
            for (int mt = 0; mt < 2; mt++)
                #pragma unroll
                for (int nt = 0; nt < 4; nt++)
                    mma_tf32(acc[mt][nt], af[mt], bf[nt]);
        }
    }

    #pragma unroll
    for (int mt = 0; mt < 2; mt++) {
        int ra = m0 + wm * 32 + mt * 16 + grp;
        int rb = ra + 8;
        #pragma unroll
        for (int nt = 0; nt < 4; nt++) {
            int o = c0 + wn * 32 + nt * 8 + 2 * qd;
            size_t ia = (size_t)ra * CC + o;
            size_t ib = (size_t)rb * CC + o;
            float2 gla = *reinterpret_cast<const float2*>(g_GL + ia);
            float2 glb = *reinterpret_cast<const float2*>(g_GL + ib);
            float2 pa  = *reinterpret_cast<const float2*>(pair + ia);
            float2 pb  = *reinterpret_cast<const float2*>(pair + ib);
            *reinterpret_cast<float2*>(out + ia) =
                make_float2(pa.x + acc[mt][nt][0] * gla.x, pa.y + acc[mt][nt][1] * gla.y);
            *reinterpret_cast<float2*>(out + ib) =
                make_float2(pb.x + acc[mt][nt][2] * glb.x, pb.y + acc[mt][nt][3] * glb.y);
        }
    }
}

// ---------------- launch --------------------------------------------------
extern "C" void kernel_launch(void* const* d_in, const int* in_sizes, int n_in,
                              void* d_out, int out_size) {
    const float* pair = (const float*)d_in[0];
    const float* mask = (const float*)d_in[1];
    const float* ln1w = (const float*)d_in[2];
    const float* ln1b = (const float*)d_in[3];
    const float* Wp   = (const float*)d_in[4];
    const float* Wg   = (const float*)d_in[5];
    const float* ln2w = (const float*)d_in[6];
    const float* ln2b = (const float*)d_in[7];
    const float* Wo   = (const float*)d_in[8];
    const float* Wgl  = (const float*)d_in[9];
    float* out = (float*)d_out;

    // 1) LN1 row stats
    k_stats<<<MM / 8, 256>>>(pair);

    // 2) proj/gate (+gl) fused GEMM -> g_AT, g_BT (tf32, channel-major), g_GL
    {
        dim3 g(4, MM / 128);
        k_proj_mma<<<g, 256>>>(pair, mask, ln1w, ln1b, Wp, Wg, Wgl);
    }

    // 3) triangle einsum (tensor, single-barrier pipeline) -> g_TRIT (C, N, N)
    {
        dim3 g(NN / 128, NN / 128, CC);
        k_tri_mma<<<g, 256>>>();
    }

    // 4) transpose to (M, C)
    {
        dim3 g(MM / 64, CC / 64);
        k_transpose<<<g, 256>>>();
    }

    // 5) output: fused LN2 stats + GEMM + gate + residual
    {
        dim3 g(2, MM / 128);
        k_out_mma<<<g, 256>>>(pair, ln2w, ln2b, Wo, out);
    }
}